// round 1
// baseline (speedup 1.0000x reference)
#include <cuda_runtime.h>

// ---------------- problem constants ----------------
#define B_    64
#define N_    482
#define DIM_  512
#define H_    8
#define D_    64
#define QKV_  1536
#define BH_   (B_*H_)          // 512
#define BN_   (B_*N_)          // 30848  (== 241*128, exact for 128-tiles)
#define SZ_BND (BN_*DIM_)      // 15794176
#define NHW_  256
#define NB_   225
#define TAIL0_ 257             // N_ - NB_
#define SCALE_ 0.125f          // DIM_HEAD^-0.5

// ---------------- device scratch (static, allowed) ----------------
__device__ float g_qkv [(size_t)BN_*QKV_];
__device__ float g_qkvm[(size_t)BN_*QKV_];
__device__ float g_qq  [(size_t)BH_*N_*D_];
__device__ float g_kk  [(size_t)BH_*N_*D_];
__device__ float g_vv  [(size_t)BH_*N_*D_];
__device__ float g_vm  [(size_t)BH_*N_*D_];
__device__ float g_dots[(size_t)BH_*N_*N_];   // 512*482*482
__device__ float g_out [SZ_BND];
__device__ float g_m   [SZ_BND];
__device__ float g_out2[SZ_BND];
__device__ float g_m2  [SZ_BND];
__device__ float g_max [B_*H_*3*D_];
__device__ float g_upd [BN_];
__device__ float g_mm  [B_*(N_-1)];

// ---------------- generic NT SGEMM, 128x128 tile, K%8==0, M%128==0, N%128==0 ----
// C[m,n] = sum_k A[m*K+k] * f(B[n*K+k]) (+ bias[n])
template<bool ABS_B, bool BIAS>
__global__ void __launch_bounds__(256) sgemm128(const float* __restrict__ A,
                                                const float* __restrict__ Bm,
                                                const float* __restrict__ bias,
                                                float* __restrict__ C,
                                                int K, int ldc)
{
    __shared__ __align__(16) float As[8][128];
    __shared__ __align__(16) float Bs[8][128];
    const int tid = threadIdx.x;
    const int bm = blockIdx.y * 128, bn = blockIdx.x * 128;
    const int lr = tid >> 1, lk = (tid & 1) * 4;
    const float* Ap = A  + (size_t)(bm + lr) * K + lk;
    const float* Bp = Bm + (size_t)(bn + lr) * K + lk;
    const int tx = tid & 15, ty = tid >> 4;

    float acc[8][8];
    #pragma unroll
    for (int i = 0; i < 8; i++)
        #pragma unroll
        for (int j = 0; j < 8; j++) acc[i][j] = 0.f;

    for (int k0 = 0; k0 < K; k0 += 8) {
        float4 av = *(const float4*)(Ap + k0);
        float4 bv = *(const float4*)(Bp + k0);
        if (ABS_B) { bv.x = fabsf(bv.x); bv.y = fabsf(bv.y); bv.z = fabsf(bv.z); bv.w = fabsf(bv.w); }
        As[lk+0][lr] = av.x; As[lk+1][lr] = av.y; As[lk+2][lr] = av.z; As[lk+3][lr] = av.w;
        Bs[lk+0][lr] = bv.x; Bs[lk+1][lr] = bv.y; Bs[lk+2][lr] = bv.z; Bs[lk+3][lr] = bv.w;
        __syncthreads();
        #pragma unroll
        for (int k = 0; k < 8; k++) {
            float rm[8], rn[8];
            *(float4*)(rm)   = *(const float4*)&As[k][ty*4];
            *(float4*)(rm+4) = *(const float4*)&As[k][64 + ty*4];
            *(float4*)(rn)   = *(const float4*)&Bs[k][tx*4];
            *(float4*)(rn+4) = *(const float4*)&Bs[k][64 + tx*4];
            #pragma unroll
            for (int i = 0; i < 8; i++)
                #pragma unroll
                for (int j = 0; j < 8; j++) acc[i][j] += rm[i] * rn[j];
        }
        __syncthreads();
    }
    #pragma unroll
    for (int i = 0; i < 8; i++) {
        int m = bm + ((i < 4) ? ty*4 + i : 64 + ty*4 + (i-4));
        #pragma unroll
        for (int jh = 0; jh < 2; jh++) {
            int n = bn + jh*64 + tx*4;
            float4 r;
            r.x = acc[i][jh*4+0]; r.y = acc[i][jh*4+1];
            r.z = acc[i][jh*4+2]; r.w = acc[i][jh*4+3];
            if (BIAS) { r.x += bias[n]; r.y += bias[n+1]; r.z += bias[n+2]; r.w += bias[n+3]; }
            *(float4*)&C[(size_t)m * ldc + n] = r;
        }
    }
}

// ---------------- updated[b,i] = (i==0) ? 1 : (sum(mask row) > 0) ----------------
__global__ void updated_k(const float* __restrict__ mask)
{
    int row = blockIdx.x * (blockDim.x >> 5) + (threadIdx.x >> 5);
    if (row >= BN_) return;
    int ln = threadIdx.x & 31;
    const float* p = mask + (size_t)row * DIM_;
    float s = 0.f;
    #pragma unroll
    for (int e = ln; e < DIM_; e += 32) s += p[e];
    #pragma unroll
    for (int o = 16; o > 0; o >>= 1) s += __shfl_xor_sync(0xffffffffu, s, o);
    if (ln == 0) {
        int i = row % N_;
        g_upd[row] = (i == 0) ? 1.0f : (s > 0.0f ? 1.0f : 0.0f);
    }
}

// ---------------- per-(b,h,w,d) max over sequence of qkv_m ----------------
__global__ void reduce_max_k()
{
    int o = blockIdx.x * blockDim.x + threadIdx.x;
    if (o >= B_*H_*3*D_) return;
    int d = o & 63;
    int w = (o >> 6) % 3;
    int h = ((o >> 6) / 3) % H_;
    int b = (o >> 6) / 24;
    const float* p = g_qkvm + (size_t)b * N_ * QKV_ + w * DIM_ + h * 64 + d;
    float mx = -1e30f;
    for (int i = 0; i < N_; i++) mx = fmaxf(mx, p[(size_t)i * QKV_]);
    g_max[o] = mx;   // layout [b][h][w][d]
}

// ---------------- build modulated q,k,v tensors in [b,h,n,d] ----------------
__global__ void modulate_k()
{
    int idx = blockIdx.x * blockDim.x + threadIdx.x;
    if (idx >= SZ_BND) return;
    int hd = idx % DIM_;
    int i  = (idx / DIM_) % N_;
    int b  = idx / (DIM_ * N_);
    int h = hd >> 6, d = hd & 63;
    size_t base = (size_t)(b * N_ + i) * QKV_;
    float q  = g_qkv [base + hd];
    float k  = g_qkv [base + DIM_ + hd];
    float v  = g_qkv [base + 2*DIM_ + hd];
    float qm = g_qkvm[base + hd];
    float km = g_qkvm[base + DIM_ + hd];
    float vm = g_qkvm[base + 2*DIM_ + hd];
    int mb = ((b * H_ + h) * 3) * 64 + d;
    float qmn = qm / (1e-6f + g_max[mb]);
    float kmn = km / (1e-6f + g_max[mb + 64]);
    float vmn = vm / (1e-6f + g_max[mb + 128]);
    size_t o = ((size_t)(b * H_ + h) * N_ + i) * D_ + d;
    g_qq[o] = q * qmn * SCALE_;   // fold softmax scale into q side
    g_kk[o] = k * kmn;
    g_vv[o] = v * vmn;
    g_vm[o] = vmn;
}

// ---------------- batched NT GEMM: dots[bh] = qq @ kk^T (K=64), bounded ----------
__global__ void __launch_bounds__(256) dots_gemm()
{
    int bh = blockIdx.z;
    const float* A  = g_qq + (size_t)bh * (N_ * D_);
    const float* Bm = g_kk + (size_t)bh * (N_ * D_);
    float* C = g_dots + (size_t)bh * N_ * N_;
    int bm = blockIdx.y * 128, bn = blockIdx.x * 128;
    __shared__ __align__(16) float As[8][128];
    __shared__ __align__(16) float Bs[8][128];
    const int tid = threadIdx.x, lr = tid >> 1, lk = (tid & 1) * 4;
    const int ar = bm + lr, br = bn + lr;
    const int tx = tid & 15, ty = tid >> 4;

    float acc[8][8];
    #pragma unroll
    for (int i = 0; i < 8; i++)
        #pragma unroll
        for (int j = 0; j < 8; j++) acc[i][j] = 0.f;

    #pragma unroll
    for (int k0 = 0; k0 < D_; k0 += 8) {
        float4 av = make_float4(0.f,0.f,0.f,0.f);
        float4 bv = make_float4(0.f,0.f,0.f,0.f);
        if (ar < N_) av = *(const float4*)(A  + (size_t)ar * D_ + k0 + lk);
        if (br < N_) bv = *(const float4*)(Bm + (size_t)br * D_ + k0 + lk);
        As[lk+0][lr] = av.x; As[lk+1][lr] = av.y; As[lk+2][lr] = av.z; As[lk+3][lr] = av.w;
        Bs[lk+0][lr] = bv.x; Bs[lk+1][lr] = bv.y; Bs[lk+2][lr] = bv.z; Bs[lk+3][lr] = bv.w;
        __syncthreads();
        #pragma unroll
        for (int k = 0; k < 8; k++) {
            float rm[8], rn[8];
            *(float4*)(rm)   = *(const float4*)&As[k][ty*4];
            *(float4*)(rm+4) = *(const float4*)&As[k][64 + ty*4];
            *(float4*)(rn)   = *(const float4*)&Bs[k][tx*4];
            *(float4*)(rn+4) = *(const float4*)&Bs[k][64 + tx*4];
            #pragma unroll
            for (int i = 0; i < 8; i++)
                #pragma unroll
                for (int j = 0; j < 8; j++) acc[i][j] += rm[i] * rn[j];
        }
        __syncthreads();
    }
    #pragma unroll
    for (int i = 0; i < 8; i++) {
        int m = bm + ((i < 4) ? ty*4 + i : 64 + ty*4 + (i-4));
        if (m < N_) {
            #pragma unroll
            for (int jh = 0; jh < 2; jh++) {
                int n = bn + jh*64 + tx*4;
                #pragma unroll
                for (int jj = 0; jj < 4; jj++)
                    if (n + jj < N_) C[(size_t)m * N_ + n + jj] = acc[i][jh*4+jj];
            }
        }
    }
}

// ---------------- row softmax over 482 elements (one block per row) ----------------
__global__ void __launch_bounds__(128) softmax_rows()
{
    size_t row = blockIdx.x;
    float* p = g_dots + row * N_;
    int tid = threadIdx.x;
    float v[4];
    float mx = -1e30f;
    #pragma unroll
    for (int e = 0; e < 4; e++) {
        int j = tid + e * 128;
        if (j < N_) { v[e] = p[j]; mx = fmaxf(mx, v[e]); } else v[e] = -1e30f;
    }
    #pragma unroll
    for (int o = 16; o > 0; o >>= 1) mx = fmaxf(mx, __shfl_xor_sync(0xffffffffu, mx, o));
    __shared__ float smax[4], ssum[4];
    int w = tid >> 5, ln = tid & 31;
    if (ln == 0) smax[w] = mx;
    __syncthreads();
    mx = fmaxf(fmaxf(smax[0], smax[1]), fmaxf(smax[2], smax[3]));
    float sum = 0.f;
    #pragma unroll
    for (int e = 0; e < 4; e++) {
        int j = tid + e * 128;
        if (j < N_) { v[e] = __expf(v[e] - mx); sum += v[e]; }
    }
    #pragma unroll
    for (int o = 16; o > 0; o >>= 1) sum += __shfl_xor_sync(0xffffffffu, sum, o);
    if (ln == 0) ssum[w] = sum;
    __syncthreads();
    float inv = 1.0f / (ssum[0] + ssum[1] + ssum[2] + ssum[3]);
    #pragma unroll
    for (int e = 0; e < 4; e++) {
        int j = tid + e * 128;
        if (j < N_) p[j] = v[e] * inv;
    }
}

// ---------------- PV: out = attn@(v*vm), m = attn@vm, epilogue: *updated, [B,n,512] --
__global__ void __launch_bounds__(256) attn_pv()
{
    int bh = blockIdx.y;
    int b = bh >> 3, h = bh & 7;
    int i0 = blockIdx.x * 128;
    const float* P  = g_dots + (size_t)bh * N_ * N_;
    const float* Vv = g_vv   + (size_t)bh * N_ * D_;
    const float* Vm = g_vm   + (size_t)bh * N_ * D_;
    __shared__ __align__(16) float Ps [32][132];
    __shared__ __align__(16) float Vvs[32][64];
    __shared__ __align__(16) float Vms[32][64];
    int tid = threadIdx.x;
    int tx = tid & 15, ty = tid >> 4;

    float a1[8][4], a2[8][4];
    #pragma unroll
    for (int i = 0; i < 8; i++)
        #pragma unroll
        for (int j = 0; j < 4; j++) { a1[i][j] = 0.f; a2[i][j] = 0.f; }

    for (int j0 = 0; j0 < N_; j0 += 32) {
        #pragma unroll
        for (int e = 0; e < 16; e++) {
            int t = tid + e * 256;
            int r = t >> 5, j = t & 31;
            float val = 0.f;
            if (i0 + r < N_ && j0 + j < N_) val = P[(size_t)(i0 + r) * N_ + j0 + j];
            Ps[j][r] = val;
        }
        #pragma unroll
        for (int e = 0; e < 8; e++) {
            int t = tid + e * 256;
            int j = t >> 6, d = t & 63;
            float v1 = 0.f, v2 = 0.f;
            if (j0 + j < N_) {
                v1 = Vv[(size_t)(j0 + j) * D_ + d];
                v2 = Vm[(size_t)(j0 + j) * D_ + d];
            }
            Vvs[j][d] = v1; Vms[j][d] = v2;
        }
        __syncthreads();
        #pragma unroll
        for (int k = 0; k < 32; k++) {
            float rm[8], rn1[4], rn2[4];
            *(float4*)(rm)   = *(const float4*)&Ps[k][ty*4];
            *(float4*)(rm+4) = *(const float4*)&Ps[k][64 + ty*4];
            *(float4*)(rn1)  = *(const float4*)&Vvs[k][tx*4];
            *(float4*)(rn2)  = *(const float4*)&Vms[k][tx*4];
            #pragma unroll
            for (int i = 0; i < 8; i++)
                #pragma unroll
                for (int j = 0; j < 4; j++) {
                    a1[i][j] += rm[i] * rn1[j];
                    a2[i][j] += rm[i] * rn2[j];
                }
        }
        __syncthreads();
    }
    #pragma unroll
    for (int i = 0; i < 8; i++) {
        int ii = (i < 4) ? ty*4 + i : 64 + ty*4 + (i-4);
        int gi = i0 + ii;
        if (gi < N_) {
            float u = g_upd[b * N_ + gi];
            size_t base = (size_t)(b * N_ + gi) * DIM_ + h * 64 + tx * 4;
            float4 r1, r2;
            r1.x = a1[i][0]*u; r1.y = a1[i][1]*u; r1.z = a1[i][2]*u; r1.w = a1[i][3]*u;
            r2.x = a2[i][0]*u; r2.y = a2[i][1]*u; r2.z = a2[i][2]*u; r2.w = a2[i][3]*u;
            *(float4*)&g_out[base] = r1;
            *(float4*)&g_m  [base] = r2;
        }
    }
}

// ---------------- overlap blending: out2/m2 = out/m + origin/bridge additions ------
__global__ void blend_k()
{
    int idx = blockIdx.x * blockDim.x + threadIdx.x;
    if (idx >= SZ_BND) return;
    int c = idx % DIM_;
    int i = (idx / DIM_) % N_;
    int b = idx / (DIM_ * N_);
    float o = g_out[idx], mv = g_m[idx];
    if (i >= 1 && i <= NHW_) {
        // grid row: add avg2x2(padded tail) * (1-updated)
        int p = i - 1, y = p >> 4, x = p & 15;
        float inv = 1.0f - g_upd[b * N_ + i];
        float s1 = 0.f, s2 = 0.f;
        #pragma unroll
        for (int dy = -1; dy <= 0; dy++)
            #pragma unroll
            for (int dx = -1; dx <= 0; dx++) {
                int r = y + dy, cc = x + dx;
                if (r >= 0 && r < 15 && cc >= 0 && cc < 15) {
                    size_t src = ((size_t)(b * N_ + TAIL0_ + r * 15 + cc)) * DIM_ + c;
                    s1 += g_out[src]; s2 += g_m[src];
                }
            }
        o  += 0.25f * s1 * inv;
        mv += 0.25f * s2 * inv;
    } else if (i >= TAIL0_) {
        // tail row: add avg2x2(grid) * (1-updated)
        int p = i - TAIL0_, r = p / 15, cc = p % 15;
        float inv = 1.0f - g_upd[b * N_ + i];
        float s1 = 0.f, s2 = 0.f;
        #pragma unroll
        for (int dy = 0; dy <= 1; dy++)
            #pragma unroll
            for (int dx = 0; dx <= 1; dx++) {
                size_t src = ((size_t)(b * N_ + 1 + (r + dy) * 16 + (cc + dx))) * DIM_ + c;
                s1 += g_out[src]; s2 += g_m[src];
            }
        o  += 0.25f * s1 * inv;
        mv += 0.25f * s2 * inv;
    }
    g_out2[idx] = o;
    g_m2[idx] = mv;
}

// ---------------- mm[b,j] = mean over channels of m2[b, j+1, :] ----------------
__global__ void mm_k()
{
    int row = blockIdx.x * (blockDim.x >> 5) + (threadIdx.x >> 5);
    if (row >= B_ * (N_ - 1)) return;
    int b = row / (N_ - 1), j = row % (N_ - 1);
    int ln = threadIdx.x & 31;
    const float* p = g_m2 + (size_t)(b * N_ + j + 1) * DIM_;
    float s = 0.f;
    #pragma unroll
    for (int e = ln; e < DIM_; e += 32) s += p[e];
    #pragma unroll
    for (int o = 16; o > 0; o >>= 1) s += __shfl_xor_sync(0xffffffffu, s, o);
    if (ln == 0) g_mm[row] = s * (1.0f / DIM_);
}

// ---------------- inter: NN upsample + center blend, [B,256,256] ----------------
__global__ void inter_k(float* __restrict__ outp)
{
    int idx = blockIdx.x * blockDim.x + threadIdx.x;
    if (idx >= B_ * 256 * 256) return;
    int x = idx & 255, y = (idx >> 8) & 255, b = idx >> 16;
    float v = g_mm[b * (N_ - 1) + (y >> 4) * 16 + (x >> 4)];
    if (y >= 8 && y < 248 && x >= 8 && x < 248) {
        float sh = g_mm[b * (N_ - 1) + 256 + ((y - 8) >> 4) * 15 + ((x - 8) >> 4)];
        v = 0.5f * (v + sh);
    }
    outp[idx] = v;
}

// ---------------- launch ----------------
extern "C" void kernel_launch(void* const* d_in, const int* in_sizes, int n_in,
                              void* d_out, int out_size)
{
    const float* x    = (const float*)d_in[0];
    const float* mask = (const float*)d_in[1];
    const float* Wqkv = (const float*)d_in[2];
    const float* Wout = (const float*)d_in[3];
    const float* bout = (const float*)d_in[4];
    float* out = (float*)d_out;

    float *p_qkv, *p_qkvm, *p_out2, *p_m2;
    cudaGetSymbolAddress((void**)&p_qkv,  g_qkv);
    cudaGetSymbolAddress((void**)&p_qkvm, g_qkvm);
    cudaGetSymbolAddress((void**)&p_out2, g_out2);
    cudaGetSymbolAddress((void**)&p_m2,   g_m2);

    // 1-2. qkv = x @ Wqkv^T ; qkv_m = mask @ |Wqkv|^T
    sgemm128<false,false><<<dim3(QKV_/128, BN_/128), 256>>>(x,    Wqkv, nullptr, p_qkv,  DIM_, QKV_);
    sgemm128<true, false><<<dim3(QKV_/128, BN_/128), 256>>>(mask, Wqkv, nullptr, p_qkvm, DIM_, QKV_);
    // 3. updated flags (independent of 1-2 but same stream, fine)
    updated_k<<<(BN_ + 7) / 8, 256>>>(mask);
    // 4. per-(b,h,w,d) sequence maxima of qkv_m
    reduce_max_k<<<(B_*H_*3*D_ + 255) / 256, 256>>>();
    // 5. modulated q,k,v in head-major layout
    modulate_k<<<(SZ_BND + 255) / 256, 256>>>();
    // 6. scores
    dots_gemm<<<dim3(4, 4, BH_), 256>>>();
    // 7. softmax
    softmax_rows<<<BH_ * N_, 128>>>();
    // 8. PV (out and m together), *updated, scatter to [B,n,512]
    attn_pv<<<dim3(4, BH_), 256>>>();
    // 9. overlap blending
    blend_k<<<(SZ_BND + 255) / 256, 256>>>();
    // 10. channel means of blended m
    mm_k<<<(B_ * (N_ - 1) + 7) / 8, 256>>>();
    // 11. inter output
    inter_k<<<(B_ * 65536 + 255) / 256, 256>>>(out + 2 * (size_t)SZ_BND);
    // 12-13. final projections straight into d_out
    sgemm128<false,true ><<<dim3(DIM_/128, BN_/128), 256>>>(p_out2, Wout, bout,    out,                    DIM_, DIM_);
    sgemm128<true, false><<<dim3(DIM_/128, BN_/128), 256>>>(p_m2,   Wout, nullptr, out + (size_t)SZ_BND,   DIM_, DIM_);
}